// round 4
// baseline (speedup 1.0000x reference)
#include <cuda_runtime.h>

// Problem constants
#define BB   32
#define CT   128      // C == CMAX
#define HH   56
#define WW   56
#define OC   256
#define KK   4
#define HID  64
#define HWN  (HH*WW)  // 3136
#define KW   9        // 3x3

// Scratch (device globals -- no runtime allocation allowed)
__device__ float g_pooled[BB * CT];
__device__ float g_attn[BB * KK];
// Synthesized per-sample weights, TRANSPOSED layout: [b][c*9+p][o]
__device__ float g_w[(size_t)BB * CT * KW * OC];

// ---------------------------------------------------------------------------
// Kernel 1: adaptive avg pool (mean over HW per (b,c))
// grid = B*C blocks of 128 threads
// ---------------------------------------------------------------------------
__global__ void pool_kernel(const float* __restrict__ x) {
    int bc = blockIdx.x;                 // b*C + c
    const float* p = x + (size_t)bc * HWN;
    float s = 0.f;
    for (int i = threadIdx.x; i < HWN; i += 128) s += p[i];
    #pragma unroll
    for (int o = 16; o; o >>= 1) s += __shfl_down_sync(0xffffffffu, s, o);
    __shared__ float wsum[4];
    if ((threadIdx.x & 31) == 0) wsum[threadIdx.x >> 5] = s;
    __syncthreads();
    if (threadIdx.x == 0) {
        float t = wsum[0] + wsum[1] + wsum[2] + wsum[3];
        g_pooled[bc] = t * (1.0f / (float)HWN);
    }
}

// ---------------------------------------------------------------------------
// Kernel 2: attention MLP + softmax.  grid = B blocks of 64 threads.
// ---------------------------------------------------------------------------
__global__ void attn_kernel(const float* __restrict__ fc1_w,
                            const float* __restrict__ fc1_b,
                            const float* __restrict__ fc2_w,
                            const float* __restrict__ fc2_b) {
    int b = blockIdx.x;
    __shared__ float ps[CT];
    __shared__ float hs[HID];
    __shared__ float ls[KK];
    int t = threadIdx.x;   // 0..63
    ps[t]      = g_pooled[b * CT + t];
    ps[t + 64] = g_pooled[b * CT + t + 64];
    __syncthreads();
    float s = fc1_b[t];
    #pragma unroll 8
    for (int c = 0; c < CT; ++c) s = fmaf(ps[c], fc1_w[t * CT + c], s);
    hs[t] = fmaxf(s, 0.f);
    __syncthreads();
    if (t < KK) {
        float l = fc2_b[t];
        #pragma unroll 8
        for (int j = 0; j < HID; ++j) l = fmaf(hs[j], fc2_w[t * HID + j], l);
        ls[t] = l;
    }
    __syncthreads();
    if (t == 0) {
        float m = fmaxf(fmaxf(ls[0], ls[1]), fmaxf(ls[2], ls[3]));
        float e0 = expf(ls[0] - m), e1 = expf(ls[1] - m);
        float e2 = expf(ls[2] - m), e3 = expf(ls[3] - m);
        float inv = 1.f / (e0 + e1 + e2 + e3);
        g_attn[b * KK + 0] = e0 * inv;
        g_attn[b * KK + 1] = e1 * inv;
        g_attn[b * KK + 2] = e2 * inv;
        g_attn[b * KK + 3] = e3 * inv;
    }
}

// ---------------------------------------------------------------------------
// Kernel 3: weight synthesis with smem transpose.
//   g_w[b][j][o] = sum_k attn[b][k] * bank[k][o][j],  j = c*9+p  (0..1151)
// grid = (16 j-tiles of 72, 8 o-tiles of 32, B), 256 threads.
// bank reads and g_w writes both fully coalesced; smem pad 73 -> conflict-free.
// ---------------------------------------------------------------------------
__global__ void synth_kernel(const float* __restrict__ bank) {
    int b  = blockIdx.z;
    int o0 = blockIdx.y * 32;
    int j0 = blockIdx.x * 72;
    __shared__ float sb[KK][32][73];
    __shared__ float sa[KK];
    int t = threadIdx.x;
    if (t < KK) sa[t] = g_attn[b * KK + t];
    for (int idx = t; idx < KK * 32 * 72; idx += 256) {
        int k = idx / (32 * 72);
        int r = idx % (32 * 72);
        int o = r / 72, j = r % 72;
        sb[k][o][j] = bank[(size_t)(k * OC + o0 + o) * (CT * KW) + j0 + j];
    }
    __syncthreads();
    for (int idx = t; idx < 32 * 72; idx += 256) {
        int o = idx & 31, j = idx >> 5;
        float v = sa[0] * sb[0][o][j] + sa[1] * sb[1][o][j]
                + sa[2] * sb[2][o][j] + sa[3] * sb[3][o][j];
        g_w[((size_t)b * (CT * KW) + j0 + j) * OC + o0 + o] = v;
    }
}

// ---------------------------------------------------------------------------
// Kernel 4: the grouped 3x3 conv, register-blocked FFMA kernel.
// CTA tile: 64 outputs x 8x8 pixels, C chunked by 8.
// Thread micro-tile: 4 o x 4 px (16 fp32 accumulators).
// grid = (49 spatial tiles, 4 o-blocks, B), 256 threads.
// ---------------------------------------------------------------------------
__global__ void __launch_bounds__(256)
conv_kernel(const float* __restrict__ x, float* __restrict__ out) {
    int tileid = blockIdx.x;            // 0..48
    int o0 = blockIdx.y * 64;
    int b  = blockIdx.z;
    int ty = tileid / 7, tx = tileid % 7;
    int y0 = ty * 8, x0 = tx * 8;

    __shared__ float xs[8][10][13];                 // pad 13 -> conflict-free
    __shared__ __align__(16) float ws[8 * 9 * 64];  // [cc*9+p][o], float4-readable

    int t = threadIdx.x;
    int og   = t >> 4;          // 0..15 -> o = o0 + og*4 + i
    int pg   = t & 15;
    int prow = pg >> 1;         // 0..7
    int pcol = (pg & 1) * 4;    // 0 or 4

    float acc[4][4];
    #pragma unroll
    for (int i = 0; i < 4; ++i)
        #pragma unroll
        for (int j = 0; j < 4; ++j) acc[i][j] = 0.f;

    const float* xb = x + (size_t)b * CT * HWN;
    const float* wb = g_w + (size_t)b * (CT * KW) * OC + o0;

    for (int c0 = 0; c0 < CT; c0 += 8) {
        __syncthreads();
        // ---- stage x tile: 8 channels x 10x10 (halo=1, zero-padded) ----
        for (int idx = t; idx < 800; idx += 256) {
            int cc  = idx / 100;
            int rem = idx % 100;
            int r = rem / 10, col = rem % 10;
            int gy = y0 + r - 1, gx = x0 + col - 1;
            float v = 0.f;
            if (gy >= 0 && gy < HH && gx >= 0 && gx < WW)
                v = xb[(size_t)(c0 + cc) * HWN + gy * WW + gx];
            xs[cc][r][col] = v;
        }
        // ---- stage w tile: 72 (cc,p) rows x 64 o, coalesced & conflict-free ----
        for (int idx = t; idx < 4608; idx += 256) {
            int o  = idx & 63;
            int jp = idx >> 6;          // 0..71
            ws[jp * 64 + o] = wb[(size_t)(c0 * 9 + jp) * OC + o];
        }
        __syncthreads();
        // ---- compute ----
        #pragma unroll
        for (int cc = 0; cc < 8; ++cc) {
            #pragma unroll
            for (int dy = 0; dy < 3; ++dy) {
                float xv[6];
                #pragma unroll
                for (int u = 0; u < 6; ++u) xv[u] = xs[cc][prow + dy][pcol + u];
                #pragma unroll
                for (int dx = 0; dx < 3; ++dx) {
                    float4 wv = *(const float4*)&ws[(cc * 9 + dy * 3 + dx) * 64 + og * 4];
                    float w0 = wv.x, w1 = wv.y, w2 = wv.z, w3 = wv.w;
                    #pragma unroll
                    for (int j = 0; j < 4; ++j) {
                        float xj = xv[dx + j];
                        acc[0][j] = fmaf(w0, xj, acc[0][j]);
                        acc[1][j] = fmaf(w1, xj, acc[1][j]);
                        acc[2][j] = fmaf(w2, xj, acc[2][j]);
                        acc[3][j] = fmaf(w3, xj, acc[3][j]);
                    }
                }
            }
        }
    }

    // ---- epilogue: 4 float4 stores, all aligned ----
    int oy = y0 + prow, ox = x0 + pcol;
    #pragma unroll
    for (int i = 0; i < 4; ++i) {
        int o = o0 + og * 4 + i;
        float4 v = make_float4(acc[i][0], acc[i][1], acc[i][2], acc[i][3]);
        *(float4*)&out[(((size_t)b * OC + o) * HH + oy) * WW + ox] = v;
    }
}

// ---------------------------------------------------------------------------
// Launch
// ---------------------------------------------------------------------------
extern "C" void kernel_launch(void* const* d_in, const int* in_sizes, int n_in,
                              void* d_out, int out_size) {
    const float* x     = (const float*)d_in[0];
    const float* bank  = (const float*)d_in[1];
    const float* fc1_w = (const float*)d_in[2];
    const float* fc1_b = (const float*)d_in[3];
    const float* fc2_w = (const float*)d_in[4];
    const float* fc2_b = (const float*)d_in[5];
    float* out = (float*)d_out;

    pool_kernel<<<BB * CT, 128>>>(x);
    attn_kernel<<<BB, 64>>>(fc1_w, fc1_b, fc2_w, fc2_b);
    synth_kernel<<<dim3(16, 8, BB), 256>>>(bank);
    conv_kernel<<<dim3(49, 4, BB), 256>>>(x, out);
}

// round 7
// speedup vs baseline: 1.0917x; 1.0917x over previous
#include <cuda_runtime.h>

// Problem constants
#define BB   32
#define CT   128      // C == CMAX
#define HH   56
#define WW   56
#define OC   256
#define KK   4
#define HID  64
#define HWN  (HH*WW)  // 3136
#define KW   9        // 3x3

// Scratch (device globals -- no runtime allocation allowed)
__device__ float g_pooled[BB * CT];
__device__ float g_attn[BB * KK];
// Synthesized per-sample weights, TRANSPOSED layout: [b][c*9+p][o]
__device__ float g_w[(size_t)BB * CT * KW * OC];

// ---- packed f32x2 helpers (Blackwell FFMA2 path, PTX-only) --------------
__device__ __forceinline__ unsigned long long pack_bcast(float v) {
    unsigned long long r;
    asm("mov.b64 %0, {%1, %1};" : "=l"(r) : "f"(v));
    return r;
}
__device__ __forceinline__ void fma2(unsigned long long& d,
                                     unsigned long long a,
                                     unsigned long long b) {
    asm("fma.rn.f32x2 %0, %1, %2, %0;" : "+l"(d) : "l"(a), "l"(b));
}
__device__ __forceinline__ void unpack2(unsigned long long v, float& lo, float& hi) {
    asm("mov.b64 {%0, %1}, %2;" : "=f"(lo), "=f"(hi) : "l"(v));
}

// ---------------------------------------------------------------------------
// Kernel 1: adaptive avg pool (mean over HW per (b,c))
// ---------------------------------------------------------------------------
__global__ void pool_kernel(const float* __restrict__ x) {
    int bc = blockIdx.x;                 // b*C + c
    const float* p = x + (size_t)bc * HWN;
    float s = 0.f;
    for (int i = threadIdx.x; i < HWN; i += 128) s += p[i];
    #pragma unroll
    for (int o = 16; o; o >>= 1) s += __shfl_down_sync(0xffffffffu, s, o);
    __shared__ float wsum[4];
    if ((threadIdx.x & 31) == 0) wsum[threadIdx.x >> 5] = s;
    __syncthreads();
    if (threadIdx.x == 0) {
        float t = wsum[0] + wsum[1] + wsum[2] + wsum[3];
        g_pooled[bc] = t * (1.0f / (float)HWN);
    }
}

// ---------------------------------------------------------------------------
// Kernel 2: attention MLP + softmax.  grid = B blocks of 64 threads.
// ---------------------------------------------------------------------------
__global__ void attn_kernel(const float* __restrict__ fc1_w,
                            const float* __restrict__ fc1_b,
                            const float* __restrict__ fc2_w,
                            const float* __restrict__ fc2_b) {
    int b = blockIdx.x;
    __shared__ float ps[CT];
    __shared__ float hs[HID];
    __shared__ float ls[KK];
    int t = threadIdx.x;   // 0..63
    ps[t]      = g_pooled[b * CT + t];
    ps[t + 64] = g_pooled[b * CT + t + 64];
    __syncthreads();
    float s = fc1_b[t];
    #pragma unroll 8
    for (int c = 0; c < CT; ++c) s = fmaf(ps[c], fc1_w[t * CT + c], s);
    hs[t] = fmaxf(s, 0.f);
    __syncthreads();
    if (t < KK) {
        float l = fc2_b[t];
        #pragma unroll 8
        for (int j = 0; j < HID; ++j) l = fmaf(hs[j], fc2_w[t * HID + j], l);
        ls[t] = l;
    }
    __syncthreads();
    if (t == 0) {
        float m = fmaxf(fmaxf(ls[0], ls[1]), fmaxf(ls[2], ls[3]));
        float e0 = expf(ls[0] - m), e1 = expf(ls[1] - m);
        float e2 = expf(ls[2] - m), e3 = expf(ls[3] - m);
        float inv = 1.f / (e0 + e1 + e2 + e3);
        g_attn[b * KK + 0] = e0 * inv;
        g_attn[b * KK + 1] = e1 * inv;
        g_attn[b * KK + 2] = e2 * inv;
        g_attn[b * KK + 3] = e3 * inv;
    }
}

// ---------------------------------------------------------------------------
// Kernel 3: weight synthesis with smem transpose.
//   g_w[b][j][o] = sum_k attn[b][k] * bank[k][o][j],  j = c*9+p  (0..1151)
// ---------------------------------------------------------------------------
__global__ void synth_kernel(const float* __restrict__ bank) {
    int b  = blockIdx.z;
    int o0 = blockIdx.y * 32;
    int j0 = blockIdx.x * 72;
    __shared__ float sb[KK][32][73];
    __shared__ float sa[KK];
    int t = threadIdx.x;
    if (t < KK) sa[t] = g_attn[b * KK + t];
    for (int idx = t; idx < KK * 32 * 72; idx += 256) {
        int k = idx / (32 * 72);
        int r = idx % (32 * 72);
        int o = r / 72, j = r % 72;
        sb[k][o][j] = bank[(size_t)(k * OC + o0 + o) * (CT * KW) + j0 + j];
    }
    __syncthreads();
    for (int idx = t; idx < 32 * 72; idx += 256) {
        int o = idx & 31, j = idx >> 5;
        float v = sa[0] * sb[0][o][j] + sa[1] * sb[1][o][j]
                + sa[2] * sb[2][o][j] + sa[3] * sb[3][o][j];
        g_w[((size_t)b * (CT * KW) + j0 + j) * OC + o0 + o] = v;
    }
}

// ---------------------------------------------------------------------------
// Kernel 4: grouped 3x3 conv, FFMA2 (f32x2) register-blocked kernel.
// CTA tile: 64 outputs x 8x8 pixels, C chunked by 8.
// Thread micro-tile: 4 o x 4 px = 8 packed f32x2 accumulators (o-pairs).
// w operand read as LDS.64 pairs (naturally contiguous in ws),
// x operand broadcast-packed (one MOV per scalar).
// grid = (49 spatial tiles, 4 o-blocks, B), 256 threads.
// ---------------------------------------------------------------------------
__global__ void __launch_bounds__(256)
conv_kernel(const float* __restrict__ x, float* __restrict__ out) {
    int tileid = blockIdx.x;            // 0..48
    int o0 = blockIdx.y * 64;
    int b  = blockIdx.z;
    int ty = tileid / 7, tx = tileid % 7;
    int y0 = ty * 8, x0 = tx * 8;

    __shared__ float xs[8][10][13];                 // pad 13 -> conflict-free
    __shared__ __align__(16) float ws[8 * 9 * 64];  // [cc*9+p][o], 8B-readable

    int t = threadIdx.x;
    int og   = t >> 4;          // 0..15 -> o = o0 + og*4 + i
    int pg   = t & 15;
    int prow = pg >> 1;         // 0..7
    int pcol = (pg & 1) * 4;    // 0 or 4

    // acc2[u][j] packs outputs (og*4+2u, og*4+2u+1) at pixel j
    unsigned long long acc2[2][4];
    #pragma unroll
    for (int u = 0; u < 2; ++u)
        #pragma unroll
        for (int j = 0; j < 4; ++j) acc2[u][j] = 0ull;

    const float* xb = x + (size_t)b * CT * HWN;
    const float* wb = g_w + (size_t)b * (CT * KW) * OC + o0;

    for (int c0 = 0; c0 < CT; c0 += 8) {
        __syncthreads();
        // ---- stage x tile: 8 channels x 10x10 (halo=1, zero-padded) ----
        for (int idx = t; idx < 800; idx += 256) {
            int cc  = idx / 100;
            int rem = idx % 100;
            int r = rem / 10, col = rem % 10;
            int gy = y0 + r - 1, gx = x0 + col - 1;
            float v = 0.f;
            if (gy >= 0 && gy < HH && gx >= 0 && gx < WW)
                v = xb[(size_t)(c0 + cc) * HWN + gy * WW + gx];
            xs[cc][r][col] = v;
        }
        // ---- stage w tile: 72 (cc,p) rows x 64 o, coalesced & conflict-free ----
        for (int idx = t; idx < 4608; idx += 256) {
            int o  = idx & 63;
            int jp = idx >> 6;          // 0..71
            ws[jp * 64 + o] = wb[(size_t)(c0 * 9 + jp) * OC + o];
        }
        __syncthreads();
        // ---- compute ----
        #pragma unroll
        for (int cc = 0; cc < 8; ++cc) {
            #pragma unroll
            for (int dy = 0; dy < 3; ++dy) {
                unsigned long long xx[6];
                #pragma unroll
                for (int u = 0; u < 6; ++u)
                    xx[u] = pack_bcast(xs[cc][prow + dy][pcol + u]);
                #pragma unroll
                for (int dx = 0; dx < 3; ++dx) {
                    const unsigned long long* wp = (const unsigned long long*)
                        &ws[(cc * 9 + dy * 3 + dx) * 64 + og * 4];
                    unsigned long long w01 = wp[0];
                    unsigned long long w23 = wp[1];
                    #pragma unroll
                    for (int j = 0; j < 4; ++j) {
                        fma2(acc2[0][j], w01, xx[dx + j]);
                        fma2(acc2[1][j], w23, xx[dx + j]);
                    }
                }
            }
        }
    }

    // ---- epilogue: unpack and store 4 aligned float4 ----
    int oy = y0 + prow, ox = x0 + pcol;
    #pragma unroll
    for (int u = 0; u < 2; ++u) {
        float lo[4], hi[4];
        #pragma unroll
        for (int j = 0; j < 4; ++j) unpack2(acc2[u][j], lo[j], hi[j]);
        int o_lo = o0 + og * 4 + 2 * u;
        float4 vlo = make_float4(lo[0], lo[1], lo[2], lo[3]);
        float4 vhi = make_float4(hi[0], hi[1], hi[2], hi[3]);
        *(float4*)&out[(((size_t)b * OC + o_lo    ) * HH + oy) * WW + ox] = vlo;
        *(float4*)&out[(((size_t)b * OC + o_lo + 1) * HH + oy) * WW + ox] = vhi;
    }
}

// ---------------------------------------------------------------------------
// Launch
// ---------------------------------------------------------------------------
extern "C" void kernel_launch(void* const* d_in, const int* in_sizes, int n_in,
                              void* d_out, int out_size) {
    const float* x     = (const float*)d_in[0];
    const float* bank  = (const float*)d_in[1];
    const float* fc1_w = (const float*)d_in[2];
    const float* fc1_b = (const float*)d_in[3];
    const float* fc2_w = (const float*)d_in[4];
    const float* fc2_b = (const float*)d_in[5];
    float* out = (float*)d_out;

    pool_kernel<<<BB * CT, 128>>>(x);
    attn_kernel<<<BB, 64>>>(fc1_w, fc1_b, fc2_w, fc2_b);
    synth_kernel<<<dim3(16, 8, BB), 256>>>(bank);
    conv_kernel<<<dim3(49, 4, BB), 256>>>(x, out);
}

// round 8
// speedup vs baseline: 1.4090x; 1.2907x over previous
#include <cuda_runtime.h>

// Problem constants
#define BB   32
#define CT   128      // C == CMAX
#define HH   56
#define WW   56
#define OC   256
#define KK   4
#define HID  64
#define HWN  (HH*WW)  // 3136
#define KW   9        // 3x3

// Scratch (device globals -- no runtime allocation allowed)
__device__ float g_pooled[BB * CT];
__device__ float g_attn[BB * KK];
// Synthesized per-sample weights, TRANSPOSED layout: [b][c*9+p][o]
__device__ float g_w[(size_t)BB * CT * KW * OC];

// ---- packed f32x2 helpers (Blackwell FFMA2 path, PTX-only) --------------
__device__ __forceinline__ unsigned long long pack_bcast(float v) {
    unsigned long long r;
    asm("mov.b64 %0, {%1, %1};" : "=l"(r) : "f"(v));
    return r;
}
__device__ __forceinline__ void fma2(unsigned long long& d,
                                     unsigned long long a,
                                     unsigned long long b) {
    asm("fma.rn.f32x2 %0, %1, %2, %0;" : "+l"(d) : "l"(a), "l"(b));
}
__device__ __forceinline__ void unpack2(unsigned long long v, float& lo, float& hi) {
    asm("mov.b64 {%0, %1}, %2;" : "=f"(lo), "=f"(hi) : "l"(v));
}

// ---------------------------------------------------------------------------
// Kernel 1: adaptive avg pool (mean over HW per (b,c))
// ---------------------------------------------------------------------------
__global__ void pool_kernel(const float* __restrict__ x) {
    int bc = blockIdx.x;                 // b*C + c
    const float* p = x + (size_t)bc * HWN;
    float s = 0.f;
    for (int i = threadIdx.x; i < HWN; i += 128) s += p[i];
    #pragma unroll
    for (int o = 16; o; o >>= 1) s += __shfl_down_sync(0xffffffffu, s, o);
    __shared__ float wsum[4];
    if ((threadIdx.x & 31) == 0) wsum[threadIdx.x >> 5] = s;
    __syncthreads();
    if (threadIdx.x == 0) {
        float t = wsum[0] + wsum[1] + wsum[2] + wsum[3];
        g_pooled[bc] = t * (1.0f / (float)HWN);
    }
}

// ---------------------------------------------------------------------------
// Kernel 2: attention MLP + softmax.  grid = B blocks of 64 threads.
// ---------------------------------------------------------------------------
__global__ void attn_kernel(const float* __restrict__ fc1_w,
                            const float* __restrict__ fc1_b,
                            const float* __restrict__ fc2_w,
                            const float* __restrict__ fc2_b) {
    int b = blockIdx.x;
    __shared__ float ps[CT];
    __shared__ float hs[HID];
    __shared__ float ls[KK];
    int t = threadIdx.x;   // 0..63
    ps[t]      = g_pooled[b * CT + t];
    ps[t + 64] = g_pooled[b * CT + t + 64];
    __syncthreads();
    float s = fc1_b[t];
    #pragma unroll 8
    for (int c = 0; c < CT; ++c) s = fmaf(ps[c], fc1_w[t * CT + c], s);
    hs[t] = fmaxf(s, 0.f);
    __syncthreads();
    if (t < KK) {
        float l = fc2_b[t];
        #pragma unroll 8
        for (int j = 0; j < HID; ++j) l = fmaf(hs[j], fc2_w[t * HID + j], l);
        ls[t] = l;
    }
    __syncthreads();
    if (t == 0) {
        float m = fmaxf(fmaxf(ls[0], ls[1]), fmaxf(ls[2], ls[3]));
        float e0 = expf(ls[0] - m), e1 = expf(ls[1] - m);
        float e2 = expf(ls[2] - m), e3 = expf(ls[3] - m);
        float inv = 1.f / (e0 + e1 + e2 + e3);
        g_attn[b * KK + 0] = e0 * inv;
        g_attn[b * KK + 1] = e1 * inv;
        g_attn[b * KK + 2] = e2 * inv;
        g_attn[b * KK + 3] = e3 * inv;
    }
}

// ---------------------------------------------------------------------------
// Kernel 3: weight synthesis with smem transpose.
//   g_w[b][j][o] = sum_k attn[b][k] * bank[k][o][j],  j = c*9+p  (0..1151)
// ---------------------------------------------------------------------------
__global__ void synth_kernel(const float* __restrict__ bank) {
    int b  = blockIdx.z;
    int o0 = blockIdx.y * 32;
    int j0 = blockIdx.x * 72;
    __shared__ float sb[KK][32][73];
    __shared__ float sa[KK];
    int t = threadIdx.x;
    if (t < KK) sa[t] = g_attn[b * KK + t];
    for (int idx = t; idx < KK * 32 * 72; idx += 256) {
        int k = idx / (32 * 72);
        int r = idx % (32 * 72);
        int o = r / 72, j = r % 72;
        sb[k][o][j] = bank[(size_t)(k * OC + o0 + o) * (CT * KW) + j0 + j];
    }
    __syncthreads();
    for (int idx = t; idx < 32 * 72; idx += 256) {
        int o = idx & 31, j = idx >> 5;
        float v = sa[0] * sb[0][o][j] + sa[1] * sb[1][o][j]
                + sa[2] * sb[2][o][j] + sa[3] * sb[3][o][j];
        g_w[((size_t)b * (CT * KW) + j0 + j) * OC + o0 + o] = v;
    }
}

// ---------------------------------------------------------------------------
// Kernel 4: grouped 3x3 conv, FFMA2 kernel with 8-o micro-tile.
// CTA tile: 128 outputs x 8x8 pixels, C chunked by 8.
// Thread micro-tile: 8 o x 4 px = 16 packed f32x2 accumulators (4 o-pairs).
// w read as LDS.128 (ulonglong2 = 2 f32x2 pairs per load),
// x broadcast-packed once per scalar (MOV), amortized over 2x the MACs.
// grid = (49 spatial tiles, 2 o-blocks, B), 256 threads.
// ---------------------------------------------------------------------------
__global__ void __launch_bounds__(256)
conv_kernel(const float* __restrict__ x, float* __restrict__ out) {
    int tileid = blockIdx.x;            // 0..48
    int o0 = blockIdx.y * 128;
    int b  = blockIdx.z;
    int ty = tileid / 7, tx = tileid % 7;
    int y0 = ty * 8, x0 = tx * 8;

    __shared__ float xs[8][10][13];                  // pad 13 -> conflict-free
    __shared__ __align__(16) float ws[8 * 9 * 128];  // [cc*9+p][o 0..127]

    int t = threadIdx.x;
    int og   = t >> 4;          // 0..15 -> 8 o's: o = o0 + og*8 + (0..7)
    int pg   = t & 15;
    int prow = pg >> 1;         // 0..7
    int pcol = (pg & 1) * 4;    // 0 or 4

    // acc2[u][j]: o-pair (og*8+2u, og*8+2u+1) at pixel j
    unsigned long long acc2[4][4];
    #pragma unroll
    for (int u = 0; u < 4; ++u)
        #pragma unroll
        for (int j = 0; j < 4; ++j) acc2[u][j] = 0ull;

    const float* xb = x + (size_t)b * CT * HWN;
    const float4* wb4 = (const float4*)(g_w + (size_t)b * (CT * KW) * OC + o0);
    // source row stride in float4 units: OC/4 = 64

    for (int c0 = 0; c0 < CT; c0 += 8) {
        __syncthreads();
        // ---- stage x tile: 8 channels x 10x10 (halo=1, zero-padded) ----
        for (int idx = t; idx < 800; idx += 256) {
            int cc  = idx / 100;
            int rem = idx % 100;
            int r = rem / 10, col = rem % 10;
            int gy = y0 + r - 1, gx = x0 + col - 1;
            float v = 0.f;
            if (gy >= 0 && gy < HH && gx >= 0 && gx < WW)
                v = xb[(size_t)(c0 + cc) * HWN + gy * WW + gx];
            xs[cc][r][col] = v;
        }
        // ---- stage w tile: 72 rows x 128 o = 2304 float4, coalesced ----
        #pragma unroll
        for (int k = 0; k < 9; ++k) {
            int idx = t + k * 256;          // 0..2303
            int jp   = idx >> 5;            // row 0..71
            int col4 = idx & 31;            // float4 within 128-o row
            ((float4*)ws)[idx] = wb4[(size_t)(c0 * 9 + jp) * 64 + col4];
        }
        __syncthreads();
        // ---- compute ----
        #pragma unroll
        for (int cc = 0; cc < 8; ++cc) {
            #pragma unroll
            for (int dy = 0; dy < 3; ++dy) {
                unsigned long long xx[6];
                #pragma unroll
                for (int u = 0; u < 6; ++u)
                    xx[u] = pack_bcast(xs[cc][prow + dy][pcol + u]);
                #pragma unroll
                for (int dx = 0; dx < 3; ++dx) {
                    const ulonglong2* wp = (const ulonglong2*)
                        &ws[(cc * 9 + dy * 3 + dx) * 128 + og * 8];
                    ulonglong2 wA = wp[0];   // o-pairs 0,1
                    ulonglong2 wB = wp[1];   // o-pairs 2,3
                    #pragma unroll
                    for (int j = 0; j < 4; ++j) {
                        unsigned long long xj = xx[dx + j];
                        fma2(acc2[0][j], wA.x, xj);
                        fma2(acc2[1][j], wA.y, xj);
                        fma2(acc2[2][j], wB.x, xj);
                        fma2(acc2[3][j], wB.y, xj);
                    }
                }
            }
        }
    }

    // ---- epilogue: unpack and store 8 aligned float4 ----
    int oy = y0 + prow, ox = x0 + pcol;
    #pragma unroll
    for (int u = 0; u < 4; ++u) {
        float lo[4], hi[4];
        #pragma unroll
        for (int j = 0; j < 4; ++j) unpack2(acc2[u][j], lo[j], hi[j]);
        int o_lo = o0 + og * 8 + 2 * u;
        float4 vlo = make_float4(lo[0], lo[1], lo[2], lo[3]);
        float4 vhi = make_float4(hi[0], hi[1], hi[2], hi[3]);
        *(float4*)&out[(((size_t)b * OC + o_lo    ) * HH + oy) * WW + ox] = vlo;
        *(float4*)&out[(((size_t)b * OC + o_lo + 1) * HH + oy) * WW + ox] = vhi;
    }
}

// ---------------------------------------------------------------------------
// Launch
// ---------------------------------------------------------------------------
extern "C" void kernel_launch(void* const* d_in, const int* in_sizes, int n_in,
                              void* d_out, int out_size) {
    const float* x     = (const float*)d_in[0];
    const float* bank  = (const float*)d_in[1];
    const float* fc1_w = (const float*)d_in[2];
    const float* fc1_b = (const float*)d_in[3];
    const float* fc2_w = (const float*)d_in[4];
    const float* fc2_b = (const float*)d_in[5];
    float* out = (float*)d_out;

    pool_kernel<<<BB * CT, 128>>>(x);
    attn_kernel<<<BB, 64>>>(fc1_w, fc1_b, fc2_w, fc2_b);
    synth_kernel<<<dim3(16, 8, BB), 256>>>(bank);
    conv_kernel<<<dim3(49, 2, BB), 256>>>(x, out);
}